// round 15
// baseline (speedup 1.0000x reference)
#include <cuda_runtime.h>
#include <cstdint>
#include <math.h>

#define Bn 32
#define Cn 224
#define Tn 2048
#define TT 32            // t-columns per stage-1 block
#define NW1 8            // warps per stage-1 block
#define CW 28            // channels per warp (8*28 = 224)
#define BC (Bn * Cn)     // 7168 sequences
#define PITCH 2304       // g_I row pitch in floats (2048 + 256 pad)
#define CHK 128          // stage-2 chunk (t-steps per ring stage)
#define SROW 132         // smem row stride in floats (128 + 4)
#define SPW 64           // stage-2 sequences per warp (2 per lane)

// Intermediate I in natural [seq][t(padded)] layout (from stage 1).
__device__ float g_I[(size_t)BC * PITCH];

#define CP_ASYNC16(dst, src) \
    asm volatile("cp.async.cg.shared.global [%0], [%1], 16;" :: "r"(dst), "l"(src) : "memory")
#define CP_COMMIT() asm volatile("cp.async.commit_group;" ::: "memory")
#define CP_WAIT1()  asm volatile("cp.async.wait_group 1;" ::: "memory")

#define BULK_S2G(gdst, ssrc, bytes) \
    asm volatile("cp.async.bulk.global.shared::cta.bulk_group [%0], [%1], %2;" \
                 :: "l"(gdst), "r"(ssrc), "r"(bytes) : "memory")
#define BULK_COMMIT() asm volatile("cp.async.bulk.commit_group;" ::: "memory")
#define BULK_WAIT1()  asm volatile("cp.async.bulk.wait_group 1;" ::: "memory")
#define BULK_WAIT0()  asm volatile("cp.async.bulk.wait_group 0;" ::: "memory")
#define FENCE_ASYNC() asm volatile("fence.proxy.async.shared::cta;" ::: "memory")

// Exact spike: spf = sat((mem - 1) * 2^46) == (mem > 1 ? 1.0f : 0.0f).
#define SPIKE(spf, mem, c1, c2) \
    asm("fma.rn.sat.f32 %0, %1, %2, %3;" : "=f"(spf) : "f"(mem), "f"(c1), "f"(c2))

// One LIF step, exact reference order: mem = (0.95*mem + v) - spk_prev
#define STEP(mem, spf, v, o, C1, C2) do {                 \
    float q_ = __fadd_rn(__fmul_rn(0.95f, (mem)), (v));   \
    (mem) = __fsub_rn(q_, (spf));                         \
    SPIKE((spf), (mem), (C1), (C2));                      \
    (o) = (spf);                                          \
} while (0)

// ---------------------------------------------------------------------------
// Stage 1 (unchanged — measured 23.2us): per (b, 32-t-tile), 256 threads.
// ---------------------------------------------------------------------------
__global__ void __launch_bounds__(256) agss_stage1(const float* __restrict__ x,
                                                   const float* __restrict__ lw) {
    __shared__ float xs[Cn * 33];          // [c][t], stride 33 (conflict-free)
    __shared__ float lws[Cn];
    __shared__ float pdot[NW1][32];
    __shared__ float kern_s[13 * TT];

    const int tid  = threadIdx.x;
    const int lane = tid & 31;
    const int wid  = tid >> 5;
    const int b    = blockIdx.y;
    const int t0   = blockIdx.x * TT;
    const int cw0  = wid * CW;

    const float* xb = x + ((size_t)b * Cn) * Tn + t0;

    if (tid < Cn) lws[tid] = lw[tid];

    #pragma unroll
    for (int i = tid; i < Cn * 8; i += 256) {
        int c = i >> 3, j = i & 7;
        float4 v = *(const float4*)(xb + (size_t)c * Tn + 4 * j);
        float* p = xs + c * 33 + 4 * j;
        p[0] = v.x; p[1] = v.y; p[2] = v.z; p[3] = v.w;
    }
    __syncthreads();

    {
        float s = 0.f, k = 0.f;
        #pragma unroll
        for (int j = 0; j < CW; j++) {
            int c = cw0 + j;
            float p  = __fmul_rn(xs[c * 33 + lane], lws[c]);
            float y  = __fsub_rn(p, k);
            float t2 = __fadd_rn(s, y);
            k = __fsub_rn(__fsub_rn(t2, s), y);
            s = t2;
        }
        pdot[wid][lane] = __fadd_rn(s, k);
    }
    __syncthreads();

    if (tid < TT) {
        float s = pdot[0][tid];
        #pragma unroll
        for (int w = 1; w < NW1; w++) s = __fadd_rn(s, pdot[w][tid]);
        float w = __fadd_rn(5.2f, __fmul_rn(s, 9.6f));
        w = fminf(fmaxf(w, 0.4f), 10.0f);
        float invw = __fdiv_rn(1.0f, w);

        float kern[13];
        #pragma unroll
        for (int k = 0; k < 13; k++) {
            float q = __fmul_rn((float)(k - 6), invw);
            kern[k] = expf(__fmul_rn(-0.5f, __fmul_rn(q, q)));
        }
        float q0 = __fmul_rn(0.93023255813953487f, invw);   // (120/129)/w
        float a  = __fmul_rn(0.5f, __fmul_rn(q0, q0));
        float rho  = expf(__fmul_rn(-2.0f, a));
        float term = expf(__fmul_rn(-0.25f, a));
        float ssum = term, qq = rho;
        #pragma unroll 8
        for (int m = 0; m < 64; m++) {
            term = __fmul_rn(term, qq);
            ssum = __fadd_rn(ssum, term);
            qq   = __fmul_rn(qq, rho);
        }
        float invn = __fdiv_rn(1.0f, __fmul_rn(2.0f, ssum));
        #pragma unroll
        for (int k = 0; k < 13; k++)
            kern_s[k * TT + tid] = __fmul_rn(kern[k], invn);
    }
    __syncthreads();

    float kk[13];
    #pragma unroll
    for (int k = 0; k < 13; k++) kk[k] = kern_s[k * TT + lane];

    float win[13];
    #pragma unroll
    for (int i = 0; i < 13; i++) {
        int c = cw0 - 6 + i;
        win[i] = (c >= 0 && c < Cn) ? xs[c * 33 + lane] : 0.0f;
    }

    float* Ib = g_I + ((size_t)b * Cn + cw0) * PITCH + t0 + lane;
    #pragma unroll
    for (int j = 0; j < CW; j++) {
        float acc = __fmul_rn(win[j % 13], kk[0]);
        #pragma unroll
        for (int i = 1; i < 13; i++)
            acc = fmaf(win[(j + i) % 13], kk[i], acc);
        float xc = win[(j + 6) % 13];
        float I  = __fsub_rn(xc, fmaxf(__fsub_rn(xc, acc), 0.0f));
        Ib[(size_t)j * PITCH] = I;
        int cn = cw0 + j + 7;
        win[j % 13] = (cn < Cn) ? xs[cn * 33 + lane] : 0.0f;
    }
}

// ---------------------------------------------------------------------------
// Stage 2: LIF scan, TWO chains per lane (64 seqs/warp, 112 one-warp blocks,
// one per SM). Chain B's instructions fill chain A's 12-cycle dependency
// bubbles inside the same warp (R13 proved >=50% issue slack exists).
// Same cp.async 3-stage input ring + double-buffered bulk-store output.
// Per-chain math bit-identical to R14 (exact reference op order).
// ---------------------------------------------------------------------------
__global__ void __launch_bounds__(32) agss_stage2(float* __restrict__ out) {
    __shared__ __align__(16) float stile[3][SPW * SROW];   // input ring (101KB)
    __shared__ __align__(16) float otile[2][SPW * SROW];   // output bufs (68KB)

    const int lane = threadIdx.x;
    const int seq0 = blockIdx.x * SPW;
    const float* gbase = g_I + (size_t)seq0 * PITCH;

    unsigned int sb = (unsigned int)__cvta_generic_to_shared(&stile[0][0]);
    unsigned int ob = (unsigned int)__cvta_generic_to_shared(&otile[0][0]);

    // prefetch chunks 0 and 1: lane covers 16B of row r (row-major, coalesced)
    #pragma unroll
    for (int k = 0; k < 2; k++) {
        #pragma unroll
        for (int r = 0; r < SPW; r++) {
            unsigned int d = sb + (unsigned int)((k * SPW * SROW + r * SROW + 4 * lane) * 4);
            const float* g = gbase + (size_t)r * PITCH + k * CHK + 4 * lane;
            CP_ASYNC16(d, g);
        }
        CP_COMMIT();
    }

    const float C1 = 70368744177664.0f;    // 2^46
    const float C2 = -70368744177664.0f;   // -2^46

    float ma = 0.0f, sa = 0.0f;            // chain A: seq0 + lane
    float mb = 0.0f, sb2 = 0.0f;           // chain B: seq0 + 32 + lane

    #pragma unroll 1
    for (int k = 0; k < Tn / CHK; k++) {
        CP_WAIT1();                 // input chunk k landed
        BULK_WAIT1();               // otile[k&1] free (chunk k-2's copies done)
        __syncwarp();

        const float* stA = &stile[0][0] + (k % 3) * (SPW * SROW) + lane * SROW;
        const float* stB = stA + 32 * SROW;
        float* otA = &otile[0][0] + (k & 1) * (SPW * SROW) + lane * SROW;
        float* otB = otA + 32 * SROW;

        float4 va = *(const float4*)(stA);
        float4 vb = *(const float4*)(stB);
        #pragma unroll
        for (int i4 = 0; i4 < CHK; i4 += 4) {
            float4 van, vbn;
            if (i4 + 4 < CHK) {
                van = *(const float4*)(stA + i4 + 4);   // next buffers
                vbn = *(const float4*)(stB + i4 + 4);
            }
            float4 oa, obv;
            STEP(ma, sa,  va.x, oa.x,  C1, C2);
            STEP(mb, sb2, vb.x, obv.x, C1, C2);
            STEP(ma, sa,  va.y, oa.y,  C1, C2);
            STEP(mb, sb2, vb.y, obv.y, C1, C2);
            STEP(ma, sa,  va.z, oa.z,  C1, C2);
            STEP(mb, sb2, vb.z, obv.z, C1, C2);
            STEP(ma, sa,  va.w, oa.w,  C1, C2);
            STEP(mb, sb2, vb.w, obv.w, C1, C2);
            *(float4*)(otA + i4) = oa;
            *(float4*)(otB + i4) = obv;
            va = van; vb = vbn;
        }

        // prefetch input chunk k+2 (row pad keeps loads in-bounds)
        #pragma unroll
        for (int r = 0; r < SPW; r++) {
            unsigned int d = sb + (unsigned int)((((k + 2) % 3) * SPW * SROW
                                + r * SROW + 4 * lane) * 4);
            const float* g = gbase + (size_t)r * PITCH + (k + 2) * CHK + 4 * lane;
            CP_ASYNC16(d, g);
        }
        CP_COMMIT();

        __syncwarp();               // all lanes' STS to otile visible
        if (lane == 0) {
            FENCE_ASYNC();          // order STS -> async proxy
            #pragma unroll
            for (int r = 0; r < SPW; r++) {
                float* gd = out + (size_t)(seq0 + r) * Tn + k * CHK;
                unsigned int ss = ob + (unsigned int)(((k & 1) * SPW * SROW + r * SROW) * 4);
                BULK_S2G(gd, ss, CHK * 4);
            }
            BULK_COMMIT();
        }
        __syncwarp();
    }
    BULK_WAIT0();                   // drain outstanding bulk stores
}

// ---------------------------------------------------------------------------
extern "C" void kernel_launch(void* const* d_in, const int* in_sizes, int n_in,
                              void* d_out, int out_size) {
    const float* inp = (const float*)d_in[0];   // (32,1,224,2048) f32
    const float* lw  = (const float*)d_in[1];   // (1,224) f32
    float* out = (float*)d_out;                 // (32,1,224,2048) f32

    dim3 g1(Tn / TT, Bn);
    agss_stage1<<<g1, 256>>>(inp, lw);
    agss_stage2<<<BC / SPW, 32>>>(out);
}

// round 16
// speedup vs baseline: 1.1924x; 1.1924x over previous
#include <cuda_runtime.h>
#include <cstdint>
#include <math.h>

#define Bn 32
#define Cn 224
#define Tn 2048
#define TT 32            // t-columns per stage-1 block
#define NW1 8            // warps per stage-1 block
#define CW 28            // channels per warp (8*28 = 224)
#define BC (Bn * Cn)     // 7168 sequences
#define PITCH 2304       // g_I row pitch in floats (2048 + 256 pad)
#define CHK 128          // stage-2 chunk (t-steps per ring stage)
#define SROW 132         // smem row stride in floats (128 + 4)

// Intermediate I in natural [seq][t(padded)] layout (from stage 1).
__device__ float g_I[(size_t)BC * PITCH];

#define CP_ASYNC16(dst, src) \
    asm volatile("cp.async.cg.shared.global [%0], [%1], 16;" :: "r"(dst), "l"(src) : "memory")
#define CP_COMMIT() asm volatile("cp.async.commit_group;" ::: "memory")
#define CP_WAIT1()  asm volatile("cp.async.wait_group 1;" ::: "memory")

#define BULK_S2G(gdst, ssrc, bytes) \
    asm volatile("cp.async.bulk.global.shared::cta.bulk_group [%0], [%1], %2;" \
                 :: "l"(gdst), "r"(ssrc), "r"(bytes) : "memory")
#define BULK_COMMIT() asm volatile("cp.async.bulk.commit_group;" ::: "memory")
#define BULK_WAIT1()  asm volatile("cp.async.bulk.wait_group 1;" ::: "memory")
#define BULK_WAIT0()  asm volatile("cp.async.bulk.wait_group 0;" ::: "memory")
#define FENCE_ASYNC() asm volatile("fence.proxy.async.shared::cta;" ::: "memory")

// Exact spike: spf = sat((mem - 1) * 2^46) == (mem > 1 ? 1.0f : 0.0f).
#define SPIKE(spf, mem, c1, c2) \
    asm("fma.rn.sat.f32 %0, %1, %2, %3;" : "=f"(spf) : "f"(mem), "f"(c1), "f"(c2))

// ---------------------------------------------------------------------------
// Stage 1 (unchanged — measured 23.2us): per (b, 32-t-tile), 256 threads.
// ---------------------------------------------------------------------------
__global__ void __launch_bounds__(256) agss_stage1(const float* __restrict__ x,
                                                   const float* __restrict__ lw) {
    __shared__ float xs[Cn * 33];          // [c][t], stride 33 (conflict-free)
    __shared__ float lws[Cn];
    __shared__ float pdot[NW1][32];
    __shared__ float kern_s[13 * TT];

    const int tid  = threadIdx.x;
    const int lane = tid & 31;
    const int wid  = tid >> 5;
    const int b    = blockIdx.y;
    const int t0   = blockIdx.x * TT;
    const int cw0  = wid * CW;

    const float* xb = x + ((size_t)b * Cn) * Tn + t0;

    if (tid < Cn) lws[tid] = lw[tid];

    #pragma unroll
    for (int i = tid; i < Cn * 8; i += 256) {
        int c = i >> 3, j = i & 7;
        float4 v = *(const float4*)(xb + (size_t)c * Tn + 4 * j);
        float* p = xs + c * 33 + 4 * j;
        p[0] = v.x; p[1] = v.y; p[2] = v.z; p[3] = v.w;
    }
    __syncthreads();

    {
        float s = 0.f, k = 0.f;
        #pragma unroll
        for (int j = 0; j < CW; j++) {
            int c = cw0 + j;
            float p  = __fmul_rn(xs[c * 33 + lane], lws[c]);
            float y  = __fsub_rn(p, k);
            float t2 = __fadd_rn(s, y);
            k = __fsub_rn(__fsub_rn(t2, s), y);
            s = t2;
        }
        pdot[wid][lane] = __fadd_rn(s, k);
    }
    __syncthreads();

    if (tid < TT) {
        float s = pdot[0][tid];
        #pragma unroll
        for (int w = 1; w < NW1; w++) s = __fadd_rn(s, pdot[w][tid]);
        float w = __fadd_rn(5.2f, __fmul_rn(s, 9.6f));
        w = fminf(fmaxf(w, 0.4f), 10.0f);
        float invw = __fdiv_rn(1.0f, w);

        float kern[13];
        #pragma unroll
        for (int k = 0; k < 13; k++) {
            float q = __fmul_rn((float)(k - 6), invw);
            kern[k] = expf(__fmul_rn(-0.5f, __fmul_rn(q, q)));
        }
        float q0 = __fmul_rn(0.93023255813953487f, invw);   // (120/129)/w
        float a  = __fmul_rn(0.5f, __fmul_rn(q0, q0));
        float rho  = expf(__fmul_rn(-2.0f, a));
        float term = expf(__fmul_rn(-0.25f, a));
        float ssum = term, qq = rho;
        #pragma unroll 8
        for (int m = 0; m < 64; m++) {
            term = __fmul_rn(term, qq);
            ssum = __fadd_rn(ssum, term);
            qq   = __fmul_rn(qq, rho);
        }
        float invn = __fdiv_rn(1.0f, __fmul_rn(2.0f, ssum));
        #pragma unroll
        for (int k = 0; k < 13; k++)
            kern_s[k * TT + tid] = __fmul_rn(kern[k], invn);
    }
    __syncthreads();

    float kk[13];
    #pragma unroll
    for (int k = 0; k < 13; k++) kk[k] = kern_s[k * TT + lane];

    float win[13];
    #pragma unroll
    for (int i = 0; i < 13; i++) {
        int c = cw0 - 6 + i;
        win[i] = (c >= 0 && c < Cn) ? xs[c * 33 + lane] : 0.0f;
    }

    float* Ib = g_I + ((size_t)b * Cn + cw0) * PITCH + t0 + lane;
    #pragma unroll
    for (int j = 0; j < CW; j++) {
        float acc = __fmul_rn(win[j % 13], kk[0]);
        #pragma unroll
        for (int i = 1; i < 13; i++)
            acc = fmaf(win[(j + i) % 13], kk[i], acc);
        float xc = win[(j + 6) % 13];
        float I  = __fsub_rn(xc, fmaxf(__fsub_rn(xc, acc), 0.0f));
        Ib[(size_t)j * PITCH] = I;
        int cn = cw0 + j + 7;
        win[j % 13] = (cn < Cn) ? xs[cn * 33 + lane] : 0.0f;
    }
}

// ---------------------------------------------------------------------------
// Stage 2: LIF scan — R14 structure, loop-carried chain shortened 12 -> 8:
//   q = FFMA(0.95, mem, v)  [single rounding, <=1ulp vs FMUL+FADD]
//   mem' = FSUB(q, spf)
//   spf  = FFMA.SAT((mem'-1)*2^46)   [off-chain; ready exactly when needed]
// Chain: FFMA(4) -> FSUB(4) = 8 cyc/step. 3 fma ops/step issue = 6 cyc rt.
// ---------------------------------------------------------------------------
__global__ void __launch_bounds__(64) agss_stage2(float* __restrict__ out) {
    __shared__ __align__(16) float stile[3][32 * SROW];   // input ring (50.7KB)
    __shared__ __align__(16) float otile[2][32 * SROW];   // output bufs (33.8KB)

    const int wsel = (blockIdx.x < 148) ? 0 : 1;          // SMSP disambiguation
    if ((threadIdx.x >> 5) != wsel) return;               // other warp exits

    const int lane = threadIdx.x & 31;
    const int seq0 = blockIdx.x * 32;
    const float* gbase = g_I + (size_t)seq0 * PITCH;

    unsigned int sb = (unsigned int)__cvta_generic_to_shared(&stile[0][0]);
    unsigned int ob = (unsigned int)__cvta_generic_to_shared(&otile[0][0]);

    // prefetch chunks 0 and 1: lane covers 16B of row r (row-major, coalesced)
    #pragma unroll
    for (int k = 0; k < 2; k++) {
        #pragma unroll
        for (int r = 0; r < 32; r++) {
            unsigned int d = sb + (unsigned int)((k * 32 * SROW + r * SROW + 4 * lane) * 4);
            const float* g = gbase + (size_t)r * PITCH + k * CHK + 4 * lane;
            CP_ASYNC16(d, g);
        }
        CP_COMMIT();
    }

    const float C1 = 70368744177664.0f;    // 2^46
    const float C2 = -70368744177664.0f;   // -2^46

    float mem = 0.0f, spf = 0.0f;
    float o0, o1, o2;

    #pragma unroll 1
    for (int k = 0; k < Tn / CHK; k++) {
        CP_WAIT1();                 // input chunk k landed
        BULK_WAIT1();               // otile[k&1] free (chunk k-2's copies done)
        __syncwarp();

        const float* st = &stile[0][0] + (k % 3) * (32 * SROW) + lane * SROW;
        float* otp = &otile[0][0] + (k & 1) * (32 * SROW) + lane * SROW;

        float4 v = *(const float4*)(st);
        #pragma unroll
        for (int i4 = 0; i4 < CHK; i4 += 4) {
            float4 vn;
            if (i4 + 4 < CHK) vn = *(const float4*)(st + i4 + 4);  // next buffer
            float q;
            // mem = fma(0.95, mem, v) - spk_prev   (chain: FFMA->FSUB = 8 cyc)
            q = __fmaf_rn(0.95f, mem, v.x);
            mem = __fsub_rn(q, spf);
            SPIKE(spf, mem, C1, C2);
            o0 = spf;
            q = __fmaf_rn(0.95f, mem, v.y);
            mem = __fsub_rn(q, spf);
            SPIKE(spf, mem, C1, C2);
            o1 = spf;
            q = __fmaf_rn(0.95f, mem, v.z);
            mem = __fsub_rn(q, spf);
            SPIKE(spf, mem, C1, C2);
            o2 = spf;
            q = __fmaf_rn(0.95f, mem, v.w);
            mem = __fsub_rn(q, spf);
            SPIKE(spf, mem, C1, C2);
            *(float4*)(otp + i4) = make_float4(o0, o1, o2, spf);
            v = vn;
        }

        // prefetch input chunk k+2 (row pad keeps loads in-bounds)
        #pragma unroll
        for (int r = 0; r < 32; r++) {
            unsigned int d = sb + (unsigned int)((((k + 2) % 3) * 32 * SROW
                                + r * SROW + 4 * lane) * 4);
            const float* g = gbase + (size_t)r * PITCH + (k + 2) * CHK + 4 * lane;
            CP_ASYNC16(d, g);
        }
        CP_COMMIT();

        __syncwarp();               // all lanes' STS to otile visible
        if (lane == 0) {
            FENCE_ASYNC();          // order STS -> async proxy
            #pragma unroll
            for (int r = 0; r < 32; r++) {
                float* gd = out + (size_t)(seq0 + r) * Tn + k * CHK;
                unsigned int ss = ob + (unsigned int)(((k & 1) * 32 * SROW + r * SROW) * 4);
                BULK_S2G(gd, ss, CHK * 4);
            }
            BULK_COMMIT();
        }
        __syncwarp();
    }
    BULK_WAIT0();                   // drain outstanding bulk stores
}

// ---------------------------------------------------------------------------
extern "C" void kernel_launch(void* const* d_in, const int* in_sizes, int n_in,
                              void* d_out, int out_size) {
    const float* inp = (const float*)d_in[0];   // (32,1,224,2048) f32
    const float* lw  = (const float*)d_in[1];   // (1,224) f32
    float* out = (float*)d_out;                 // (32,1,224,2048) f32

    dim3 g1(Tn / TT, Bn);
    agss_stage1<<<g1, 256>>>(inp, lw);
    agss_stage2<<<BC / 32, 64>>>(out);
}

// round 17
// speedup vs baseline: 1.2286x; 1.0304x over previous
#include <cuda_runtime.h>
#include <cstdint>
#include <math.h>

#define Bn 32
#define Cn 224
#define Tn 2048
#define TT 32            // t-columns per stage-1 block
#define NW1 8            // warps per stage-1 block
#define CW 28            // channels per warp (8*28 = 224)
#define BC (Bn * Cn)     // 7168 sequences
#define PITCH 2304       // g_I row pitch in floats (2048 + 256 pad)
#define CHK 256          // stage-2 chunk (t-steps per ring stage)
#define SROW 260         // smem row stride in floats (256 + 4 pad)

// Intermediate I in natural [seq][t(padded)] layout (from stage 1).
__device__ float g_I[(size_t)BC * PITCH];

#define CP_ASYNC16(dst, src) \
    asm volatile("cp.async.cg.shared.global [%0], [%1], 16;" :: "r"(dst), "l"(src) : "memory")
#define CP_COMMIT() asm volatile("cp.async.commit_group;" ::: "memory")
#define CP_WAIT1()  asm volatile("cp.async.wait_group 1;" ::: "memory")

#define BULK_S2G(gdst, ssrc, bytes) \
    asm volatile("cp.async.bulk.global.shared::cta.bulk_group [%0], [%1], %2;" \
                 :: "l"(gdst), "r"(ssrc), "r"(bytes) : "memory")
#define BULK_COMMIT() asm volatile("cp.async.bulk.commit_group;" ::: "memory")
#define BULK_WAIT1()  asm volatile("cp.async.bulk.wait_group 1;" ::: "memory")
#define BULK_WAIT0()  asm volatile("cp.async.bulk.wait_group 0;" ::: "memory")
#define FENCE_ASYNC() asm volatile("fence.proxy.async.shared::cta;" ::: "memory")

// Exact spike: spf = sat((mem - 1) * 2^46) == (mem > 1 ? 1.0f : 0.0f).
#define SPIKE(spf, mem, c1, c2) \
    asm("fma.rn.sat.f32 %0, %1, %2, %3;" : "=f"(spf) : "f"(mem), "f"(c1), "f"(c2))

// 4 LIF steps from one float4, spikes packed to one STS.128.
// Chain per step: FFMA(4) -> FSUB(4) = 8 cyc; SPIKE off-chain.
#define PROC4(vv, optr) do {                                        \
    float q_, o0_, o1_, o2_;                                        \
    q_ = __fmaf_rn(0.95f, mem, (vv).x);                             \
    mem = __fsub_rn(q_, spf); SPIKE(spf, mem, C1, C2); o0_ = spf;   \
    q_ = __fmaf_rn(0.95f, mem, (vv).y);                             \
    mem = __fsub_rn(q_, spf); SPIKE(spf, mem, C1, C2); o1_ = spf;   \
    q_ = __fmaf_rn(0.95f, mem, (vv).z);                             \
    mem = __fsub_rn(q_, spf); SPIKE(spf, mem, C1, C2); o2_ = spf;   \
    q_ = __fmaf_rn(0.95f, mem, (vv).w);                             \
    mem = __fsub_rn(q_, spf); SPIKE(spf, mem, C1, C2);              \
    *(float4*)(optr) = make_float4(o0_, o1_, o2_, spf);             \
} while (0)

// ---------------------------------------------------------------------------
// Stage 1 (unchanged — measured 23.2us): per (b, 32-t-tile), 256 threads.
// ---------------------------------------------------------------------------
__global__ void __launch_bounds__(256) agss_stage1(const float* __restrict__ x,
                                                   const float* __restrict__ lw) {
    __shared__ float xs[Cn * 33];          // [c][t], stride 33 (conflict-free)
    __shared__ float lws[Cn];
    __shared__ float pdot[NW1][32];
    __shared__ float kern_s[13 * TT];

    const int tid  = threadIdx.x;
    const int lane = tid & 31;
    const int wid  = tid >> 5;
    const int b    = blockIdx.y;
    const int t0   = blockIdx.x * TT;
    const int cw0  = wid * CW;

    const float* xb = x + ((size_t)b * Cn) * Tn + t0;

    if (tid < Cn) lws[tid] = lw[tid];

    #pragma unroll
    for (int i = tid; i < Cn * 8; i += 256) {
        int c = i >> 3, j = i & 7;
        float4 v = *(const float4*)(xb + (size_t)c * Tn + 4 * j);
        float* p = xs + c * 33 + 4 * j;
        p[0] = v.x; p[1] = v.y; p[2] = v.z; p[3] = v.w;
    }
    __syncthreads();

    {
        float s = 0.f, k = 0.f;
        #pragma unroll
        for (int j = 0; j < CW; j++) {
            int c = cw0 + j;
            float p  = __fmul_rn(xs[c * 33 + lane], lws[c]);
            float y  = __fsub_rn(p, k);
            float t2 = __fadd_rn(s, y);
            k = __fsub_rn(__fsub_rn(t2, s), y);
            s = t2;
        }
        pdot[wid][lane] = __fadd_rn(s, k);
    }
    __syncthreads();

    if (tid < TT) {
        float s = pdot[0][tid];
        #pragma unroll
        for (int w = 1; w < NW1; w++) s = __fadd_rn(s, pdot[w][tid]);
        float w = __fadd_rn(5.2f, __fmul_rn(s, 9.6f));
        w = fminf(fmaxf(w, 0.4f), 10.0f);
        float invw = __fdiv_rn(1.0f, w);

        float kern[13];
        #pragma unroll
        for (int k = 0; k < 13; k++) {
            float q = __fmul_rn((float)(k - 6), invw);
            kern[k] = expf(__fmul_rn(-0.5f, __fmul_rn(q, q)));
        }
        float q0 = __fmul_rn(0.93023255813953487f, invw);   // (120/129)/w
        float a  = __fmul_rn(0.5f, __fmul_rn(q0, q0));
        float rho  = expf(__fmul_rn(-2.0f, a));
        float term = expf(__fmul_rn(-0.25f, a));
        float ssum = term, qq = rho;
        #pragma unroll 8
        for (int m = 0; m < 64; m++) {
            term = __fmul_rn(term, qq);
            ssum = __fadd_rn(ssum, term);
            qq   = __fmul_rn(qq, rho);
        }
        float invn = __fdiv_rn(1.0f, __fmul_rn(2.0f, ssum));
        #pragma unroll
        for (int k = 0; k < 13; k++)
            kern_s[k * TT + tid] = __fmul_rn(kern[k], invn);
    }
    __syncthreads();

    float kk[13];
    #pragma unroll
    for (int k = 0; k < 13; k++) kk[k] = kern_s[k * TT + lane];

    float win[13];
    #pragma unroll
    for (int i = 0; i < 13; i++) {
        int c = cw0 - 6 + i;
        win[i] = (c >= 0 && c < Cn) ? xs[c * 33 + lane] : 0.0f;
    }

    float* Ib = g_I + ((size_t)b * Cn + cw0) * PITCH + t0 + lane;
    #pragma unroll
    for (int j = 0; j < CW; j++) {
        float acc = __fmul_rn(win[j % 13], kk[0]);
        #pragma unroll
        for (int i = 1; i < 13; i++)
            acc = fmaf(win[(j + i) % 13], kk[i], acc);
        float xc = win[(j + 6) % 13];
        float I  = __fsub_rn(xc, fmaxf(__fsub_rn(xc, acc), 0.0f));
        Ib[(size_t)j * PITCH] = I;
        int cn = cw0 + j + 7;
        win[j % 13] = (cn < Cn) ? xs[cn * 33 + lane] : 0.0f;
    }
}

// ---------------------------------------------------------------------------
// Stage 2: LIF scan — R16 math verbatim, issue-trimmed pipeline:
//   CHK=256, 2-stage input ring (prefetch k+2 after processing k),
//   single otile with split A/B bulk flush (wait cover >= 128 steps),
//   4-buffer rotation kills the per-iteration float4 MOV copies.
// smem 97.5KB -> 2 blocks/SM co-residency preserved.
// ---------------------------------------------------------------------------
__global__ void __launch_bounds__(64) agss_stage2(float* __restrict__ out) {
    __shared__ __align__(16) float stile[2][32 * SROW];   // input ring (66.6KB)
    __shared__ __align__(16) float otile[32 * SROW];      // output buf (33.3KB)

    const int wsel = (blockIdx.x < 148) ? 0 : 1;          // SMSP disambiguation
    if ((threadIdx.x >> 5) != wsel) return;               // other warp exits

    const int lane = threadIdx.x & 31;
    const int seq0 = blockIdx.x * 32;
    const float* gbase = g_I + (size_t)seq0 * PITCH;

    unsigned int sb = (unsigned int)__cvta_generic_to_shared(&stile[0][0]);
    unsigned int ob = (unsigned int)__cvta_generic_to_shared(&otile[0]);

    // prefetch chunks 0 and 1 into stages 0, 1 (each row = 1KB = 2 x 512B passes)
    #pragma unroll
    for (int k = 0; k < 2; k++) {
        #pragma unroll
        for (int r = 0; r < 32; r++) {
            unsigned int d = sb + (unsigned int)((k * 32 * SROW + r * SROW + 4 * lane) * 4);
            const float* g = gbase + (size_t)r * PITCH + k * CHK + 4 * lane;
            CP_ASYNC16(d, g);
            CP_ASYNC16(d + 512, g + 128);
        }
        CP_COMMIT();
    }

    const float C1 = 70368744177664.0f;    // 2^46
    const float C2 = -70368744177664.0f;   // -2^46

    float mem = 0.0f, spf = 0.0f;

    #pragma unroll 1
    for (int k = 0; k < Tn / CHK; k++) {
        CP_WAIT1();                 // input chunk k landed (per-lane groups)
        BULK_WAIT1();               // lane0: A_{k-1} drained (B_{k-1} may fly)
        __syncwarp();

        const float* st = &stile[0][0] + (k & 1) * (32 * SROW) + lane * SROW;
        float* otp = &otile[0] + lane * SROW;

        // ---- first half: steps 0..127 ----
        {
            float4 v0 = *(const float4*)(st + 0);
            float4 v1 = *(const float4*)(st + 4);
            #pragma unroll
            for (int i = 0; i < 128; i += 16) {
                float4 t0 = *(const float4*)(st + i + 8);
                PROC4(v0, otp + i);
                float4 t1 = *(const float4*)(st + i + 12);
                PROC4(v1, otp + i + 4);
                v0 = *(const float4*)(st + i + 16);
                PROC4(t0, otp + i + 8);
                v1 = *(const float4*)(st + i + 20);
                PROC4(t1, otp + i + 12);
            }
        }
        __syncwarp();               // otile[0..128) complete
        if (lane == 0) {
            FENCE_ASYNC();
            #pragma unroll
            for (int r = 0; r < 32; r++)
                BULK_S2G(out + (size_t)(seq0 + r) * Tn + k * CHK,
                         ob + (unsigned int)(r * SROW * 4), 512);
            BULK_COMMIT();          // group A_k
            BULK_WAIT1();           // B_{k-1} drained before otile[128..) reuse
        }
        __syncwarp();

        // ---- second half: steps 128..255 ----
        {
            float4 v0 = *(const float4*)(st + 128);
            float4 v1 = *(const float4*)(st + 132);
            #pragma unroll
            for (int i = 128; i < 256; i += 16) {
                float4 t0 = *(const float4*)(st + i + 8);
                PROC4(v0, otp + i);
                float4 t1 = *(const float4*)(st + i + 12);
                PROC4(v1, otp + i + 4);
                v0 = *(const float4*)(st + i + 16);   // last trip: row pad (unused)
                PROC4(t0, otp + i + 8);
                v1 = *(const float4*)(st + i + 20);   // last trip: pad/next row (unused)
                PROC4(t1, otp + i + 12);
            }
        }

        // prefetch input chunk k+2 into the just-finished stage (k & 1)
        if (k + 2 < Tn / CHK + 1) {   // k+2 <= 8; k=7 reads pad region (in-bounds)
            #pragma unroll
            for (int r = 0; r < 32; r++) {
                unsigned int d = sb + (unsigned int)(((k & 1) * 32 * SROW + r * SROW + 4 * lane) * 4);
                const float* g = gbase + (size_t)r * PITCH + (k + 2) * CHK + 4 * lane;
                CP_ASYNC16(d, g);
                CP_ASYNC16(d + 512, g + 128);
            }
            CP_COMMIT();
        }

        __syncwarp();               // otile[128..256) complete
        if (lane == 0) {
            FENCE_ASYNC();
            #pragma unroll
            for (int r = 0; r < 32; r++)
                BULK_S2G(out + (size_t)(seq0 + r) * Tn + k * CHK + 128,
                         ob + (unsigned int)((r * SROW + 128) * 4), 512);
            BULK_COMMIT();          // group B_k
        }
        __syncwarp();
    }
    BULK_WAIT0();                   // drain outstanding bulk stores
}

// ---------------------------------------------------------------------------
extern "C" void kernel_launch(void* const* d_in, const int* in_sizes, int n_in,
                              void* d_out, int out_size) {
    const float* inp = (const float*)d_in[0];   // (32,1,224,2048) f32
    const float* lw  = (const float*)d_in[1];   // (1,224) f32
    float* out = (float*)d_out;                 // (32,1,224,2048) f32

    dim3 g1(Tn / TT, Bn);
    agss_stage1<<<g1, 256>>>(inp, lw);
    agss_stage2<<<BC / 32, 64>>>(out);
}